// round 1
// baseline (speedup 1.0000x reference)
#include <cuda_runtime.h>
#include <cuda_bf16.h>

// Problem constants: B=2, T=2048, C=1024, H=16, hd=64
#define BB   2
#define TT   2048
#define CC   1024
#define HH   16
#define HD   64
#define BT   (BB*TT)          // 4096 rows
#define QKV_N (3*CC)          // 3072

// Scratch (device globals — no allocations allowed)
__device__ float g_q[BB*HH*TT*HD];   // q in [B,H,T,hd]
__device__ float g_y[BB*TT*CC];      // attention output in [B,T,C]

// ---------------------------------------------------------------------------
// SGEMM: C[M,N] = A[M,K] @ B[K,N] + bias, 128x128x8 tiles, 8x8 per thread.
// MODE 0: qkv epilogue — scatter q -> g_q, k -> out0, v -> out1 in [B,H,T,hd].
// MODE 1: plain epilogue — A is g_y, write out0[row*N+col].
// ---------------------------------------------------------------------------
template<int MODE>
__global__ __launch_bounds__(256)
void sgemm_kernel(const float* __restrict__ A,
                  const float* __restrict__ Bm,
                  const float* __restrict__ bias,
                  float* __restrict__ out0,
                  float* __restrict__ out1,
                  int N)
{
    __shared__ float As[8][128];
    __shared__ float Bs[8][128];

    const float* Ap = (MODE == 1) ? (const float*)g_y : A;

    const int tid = threadIdx.x;
    const int mB = blockIdx.y, nB = blockIdx.x;
    const int m_base = (tid / 16) * 8;
    const int n_base = (tid % 16) * 8;
    const int Kd = CC;

    float acc[8][8];
    #pragma unroll
    for (int i = 0; i < 8; i++)
        #pragma unroll
        for (int j = 0; j < 8; j++) acc[i][j] = 0.0f;

    // A-tile load coords: 128x8 floats, 1 float4 per thread
    const int arow = tid >> 1;          // 0..127
    const int acol = (tid & 1) * 4;     // 0 or 4
    // B-tile load coords: 8x128 floats, 1 float4 per thread
    const int brow = tid >> 5;          // 0..7
    const int bcol = (tid & 31) * 4;    // 0..124

    const float* Aptr = Ap + (size_t)(mB * 128 + arow) * Kd + acol;
    const float* Bptr = Bm + (size_t)brow * N + nB * 128 + bcol;

    for (int k0 = 0; k0 < Kd; k0 += 8) {
        float4 av = *(const float4*)(Aptr + k0);
        As[acol + 0][arow] = av.x;
        As[acol + 1][arow] = av.y;
        As[acol + 2][arow] = av.z;
        As[acol + 3][arow] = av.w;
        float4 bv = *(const float4*)(Bptr + (size_t)k0 * N);
        *(float4*)&Bs[brow][bcol] = bv;
        __syncthreads();

        #pragma unroll
        for (int k = 0; k < 8; k++) {
            float a[8], b[8];
            #pragma unroll
            for (int i = 0; i < 8; i++) a[i] = As[k][m_base + i];
            #pragma unroll
            for (int j = 0; j < 8; j++) b[j] = Bs[k][n_base + j];
            #pragma unroll
            for (int i = 0; i < 8; i++)
                #pragma unroll
                for (int j = 0; j < 8; j++)
                    acc[i][j] = fmaf(a[i], b[j], acc[i][j]);
        }
        __syncthreads();
    }

    // Epilogue
    #pragma unroll
    for (int i = 0; i < 8; i++) {
        const int row = mB * 128 + m_base + i;   // 0..4095
        #pragma unroll
        for (int j = 0; j < 8; j++) {
            const int col = nB * 128 + n_base + j;
            float v = acc[i][j] + bias[col];
            if (MODE == 0) {
                const int b = row >> 11;          // /2048
                const int t = row & 2047;
                const int which = col >> 10;      // 0=q 1=k 2=v
                const int cj = col & 1023;
                const int h = cj >> 6;
                const int d = cj & 63;
                const int idx = (((b * HH + h) * TT) + t) * HD + d;
                if (which == 0)      g_q[idx] = v;
                else if (which == 1) out0[idx] = v;
                else                 out1[idx] = v;
            } else {
                out0[(size_t)row * N + col] = v;
            }
        }
    }
}

// ---------------------------------------------------------------------------
// Flash-attention (causal), fp32. One block = one (b,h) x 64-query tile.
// 256 threads; thread (ty,tx) owns a 4x4 micro-tile of S/O.
// smem (dynamic): Qs,Ks,Vs,Ps each 64x65 floats (pad -> conflict-free).
// ---------------------------------------------------------------------------
#define ATT_STRIDE 65
#define ATT_SMEM   (4 * 64 * ATT_STRIDE * (int)sizeof(float))

__global__ __launch_bounds__(256)
void attn_kernel(const float* __restrict__ Kg, const float* __restrict__ Vg)
{
    extern __shared__ float sm[];
    float* Qs = sm;
    float* Ks = sm + 1 * 64 * ATT_STRIDE;
    float* Vs = sm + 2 * 64 * ATT_STRIDE;
    float* Ps = sm + 3 * 64 * ATT_STRIDE;

    const int tid = threadIdx.x;
    const int bh = blockIdx.y;          // b*16 + h
    const int qt = blockIdx.x;          // query tile
    const int q0 = qt * 64;

    const float* Qb = g_q + (size_t)bh * TT * HD;
    const float* Kb = Kg  + (size_t)bh * TT * HD;
    const float* Vb = Vg  + (size_t)bh * TT * HD;

    // Load Q tile [64 x 64] (16 floats per thread as 4 x float4)
    #pragma unroll
    for (int i = 0; i < 4; i++) {
        int lin = (i * 256 + tid) * 4;
        int row = lin >> 6, col = lin & 63;
        float4 v = *(const float4*)(Qb + (size_t)(q0 + row) * HD + col);
        float* d = Qs + row * ATT_STRIDE + col;
        d[0] = v.x; d[1] = v.y; d[2] = v.z; d[3] = v.w;
    }

    const int ty = tid / 16, tx = tid % 16;
    float m[4], l[4], o[4][4];
    #pragma unroll
    for (int i = 0; i < 4; i++) {
        m[i] = -1e30f; l[i] = 0.0f;
        #pragma unroll
        for (int j = 0; j < 4; j++) o[i][j] = 0.0f;
    }

    for (int kt = 0; kt <= qt; kt++) {
        // Load K, V tiles
        #pragma unroll
        for (int i = 0; i < 4; i++) {
            int lin = (i * 256 + tid) * 4;
            int row = lin >> 6, col = lin & 63;
            float4 kv = *(const float4*)(Kb + (size_t)(kt * 64 + row) * HD + col);
            float* dk = Ks + row * ATT_STRIDE + col;
            dk[0] = kv.x; dk[1] = kv.y; dk[2] = kv.z; dk[3] = kv.w;
            float4 vv = *(const float4*)(Vb + (size_t)(kt * 64 + row) * HD + col);
            float* dv = Vs + row * ATT_STRIDE + col;
            dv[0] = vv.x; dv[1] = vv.y; dv[2] = vv.z; dv[3] = vv.w;
        }
        __syncthreads();

        // S = Q @ K^T (4x4 per thread over d=64)
        float s[4][4];
        #pragma unroll
        for (int i = 0; i < 4; i++)
            #pragma unroll
            for (int j = 0; j < 4; j++) s[i][j] = 0.0f;

        #pragma unroll 4
        for (int d = 0; d < 64; d++) {
            float qv[4], kvv[4];
            #pragma unroll
            for (int i = 0; i < 4; i++) qv[i]  = Qs[(ty * 4 + i) * ATT_STRIDE + d];
            #pragma unroll
            for (int j = 0; j < 4; j++) kvv[j] = Ks[(tx * 4 + j) * ATT_STRIDE + d];
            #pragma unroll
            for (int i = 0; i < 4; i++)
                #pragma unroll
                for (int j = 0; j < 4; j++)
                    s[i][j] = fmaf(qv[i], kvv[j], s[i][j]);
        }

        // scale + causal mask (only diagonal tile needs masking)
        #pragma unroll
        for (int i = 0; i < 4; i++)
            #pragma unroll
            for (int j = 0; j < 4; j++) {
                float sv = s[i][j] * 0.125f;  // 1/sqrt(64)
                if (kt == qt && (kt * 64 + tx * 4 + j) > (q0 + ty * 4 + i))
                    sv = -1e30f;
                s[i][j] = sv;
            }

        // Online softmax per row (16 threads share a row; same warp half)
        #pragma unroll
        for (int i = 0; i < 4; i++) {
            float rmax = fmaxf(fmaxf(s[i][0], s[i][1]), fmaxf(s[i][2], s[i][3]));
            #pragma unroll
            for (int off = 1; off < 16; off <<= 1)
                rmax = fmaxf(rmax, __shfl_xor_sync(0xffffffffu, rmax, off));
            const float mnew = fmaxf(m[i], rmax);
            const float corr = __expf(m[i] - mnew);
            float p[4], rsum = 0.0f;
            #pragma unroll
            for (int j = 0; j < 4; j++) { p[j] = __expf(s[i][j] - mnew); rsum += p[j]; }
            #pragma unroll
            for (int off = 1; off < 16; off <<= 1)
                rsum += __shfl_xor_sync(0xffffffffu, rsum, off);
            l[i] = l[i] * corr + rsum;
            m[i] = mnew;
            #pragma unroll
            for (int j = 0; j < 4; j++) o[i][j] *= corr;
            #pragma unroll
            for (int j = 0; j < 4; j++)
                Ps[(ty * 4 + i) * ATT_STRIDE + tx * 4 + j] = p[j];
        }
        __syncthreads();

        // O += P @ V
        #pragma unroll 4
        for (int c = 0; c < 64; c++) {
            float pv[4], vv[4];
            #pragma unroll
            for (int i = 0; i < 4; i++) pv[i] = Ps[(ty * 4 + i) * ATT_STRIDE + c];
            #pragma unroll
            for (int j = 0; j < 4; j++) vv[j] = Vs[c * ATT_STRIDE + tx * 4 + j];
            #pragma unroll
            for (int i = 0; i < 4; i++)
                #pragma unroll
                for (int j = 0; j < 4; j++)
                    o[i][j] = fmaf(pv[i], vv[j], o[i][j]);
        }
        __syncthreads();
    }

    // Write O/l to y scratch in [B,T,C] layout
    const int b = bh / HH, h = bh % HH;
    #pragma unroll
    for (int i = 0; i < 4; i++) {
        const float inv = 1.0f / l[i];
        const int t = q0 + ty * 4 + i;
        #pragma unroll
        for (int j = 0; j < 4; j++)
            g_y[((size_t)(b * TT + t)) * CC + h * HD + tx * 4 + j] = o[i][j] * inv;
    }
}

// ---------------------------------------------------------------------------
extern "C" void kernel_launch(void* const* d_in, const int* in_sizes, int n_in,
                              void* d_out, int out_size)
{
    const float* x      = (const float*)d_in[0];
    const float* W_attn = (const float*)d_in[1];
    const float* b_attn = (const float*)d_in[2];
    const float* W_proj = (const float*)d_in[3];
    const float* b_proj = (const float*)d_in[4];

    float* out  = (float*)d_out;               // y: [B,T,C]
    float* kout = out  + (size_t)BB * TT * CC; // k: [B,H,T,hd]
    float* vout = kout + (size_t)BB * HH * TT * HD;

    // 1) QKV GEMM + bias + split/transpose scatter
    sgemm_kernel<0><<<dim3(QKV_N / 128, BT / 128), 256>>>(
        x, W_attn, b_attn, kout, vout, QKV_N);

    // 2) causal flash attention
    cudaFuncSetAttribute(attn_kernel,
                         cudaFuncAttributeMaxDynamicSharedMemorySize, ATT_SMEM);
    attn_kernel<<<dim3(TT / 64, BB * HH), 256, ATT_SMEM>>>(kout, vout);

    // 3) output projection + bias
    sgemm_kernel<1><<<dim3(CC / 128, BT / 128), 256>>>(
        nullptr, W_proj, b_proj, out, nullptr, CC);
}

// round 2
// speedup vs baseline: 1.2482x; 1.2482x over previous
#include <cuda_runtime.h>
#include <cuda_bf16.h>

// Problem constants: B=2, T=2048, C=1024, H=16, hd=64
#define BB   2
#define TT   2048
#define CC   1024
#define HH   16
#define HD   64
#define BT   (BB*TT)          // 4096 rows
#define QKV_N (3*CC)          // 3072

// Scratch (device globals — no allocations allowed)
__device__ float g_q[BB*HH*TT*HD];   // q in [B,H,T,hd]
__device__ float g_y[BB*TT*CC];      // attention output in [B,T,C]

// ---------------------------------------------------------------------------
// SGEMM v2: C[M,N] = A[M,K=1024] @ B[K,N] + bias.
// 128x128 tile, K-panel 16, double-buffered smem, 8x8 microtile (split 4+4
// with 64 offset), float4 smem fragment loads. 1 __syncthreads per panel.
// MODE 0: qkv epilogue (scatter q->g_q, k->out0, v->out1 in [B,H,T,hd]).
// MODE 1: A := g_y, plain epilogue to out0.
// ---------------------------------------------------------------------------
template<int MODE>
__global__ __launch_bounds__(256, 2)
void sgemm_kernel(const float* __restrict__ A,
                  const float* __restrict__ Bm,
                  const float* __restrict__ bias,
                  float* __restrict__ out0,
                  float* __restrict__ out1,
                  int N)
{
    __shared__ float As[2][16][128];   // As[k][m]
    __shared__ float Bs[2][16][128];   // Bs[k][n]

    const float* Ap = (MODE == 1) ? (const float*)g_y : A;

    const int tid = threadIdx.x;
    const int mB = blockIdx.y, nB = blockIdx.x;
    const int rm = (tid >> 4) * 4;      // rows rm..rm+3, rm+64..rm+67
    const int cn = (tid & 15) * 4;      // cols cn..cn+3, cn+64..cn+67

    // A tile loads: 128 rows x 16 cols; thread -> (ar, ac) and (ar+64, ac)
    const int ar = tid >> 2;            // 0..63
    const int ac = (tid & 3) * 4;       // 0,4,8,12
    // B tile loads: 16 rows x 128 cols; thread -> (br, bc) and (br+8, bc)
    const int br = tid >> 5;            // 0..7
    const int bc = (tid & 31) * 4;

    const float* Aptr = Ap + (size_t)(mB * 128 + ar) * CC + ac;
    const float* Bptr = Bm + (size_t)br * N + nB * 128 + bc;

    float acc[8][8];
    #pragma unroll
    for (int i = 0; i < 8; i++)
        #pragma unroll
        for (int j = 0; j < 8; j++) acc[i][j] = 0.0f;

    // preload stage 0
    {
        float4 a0 = *(const float4*)(Aptr);
        float4 a1 = *(const float4*)(Aptr + (size_t)64 * CC);
        float4 b0 = *(const float4*)(Bptr);
        float4 b1 = *(const float4*)(Bptr + (size_t)8 * N);
        As[0][ac+0][ar] = a0.x; As[0][ac+1][ar] = a0.y;
        As[0][ac+2][ar] = a0.z; As[0][ac+3][ar] = a0.w;
        As[0][ac+0][ar+64] = a1.x; As[0][ac+1][ar+64] = a1.y;
        As[0][ac+2][ar+64] = a1.z; As[0][ac+3][ar+64] = a1.w;
        *(float4*)&Bs[0][br][bc] = b0;
        *(float4*)&Bs[0][br+8][bc] = b1;
    }

    const int nk = CC / 16;   // 64 panels
    for (int kt = 0; kt < nk; kt++) {
        __syncthreads();
        const int cur = kt & 1;
        float4 na0, na1, nb0, nb1;
        const bool more = (kt + 1 < nk);
        if (more) {
            const float* Ak = Aptr + (kt + 1) * 16;
            na0 = *(const float4*)(Ak);
            na1 = *(const float4*)(Ak + (size_t)64 * CC);
            const float* Bk = Bptr + (size_t)(kt + 1) * 16 * N;
            nb0 = *(const float4*)(Bk);
            nb1 = *(const float4*)(Bk + (size_t)8 * N);
        }
        #pragma unroll
        for (int k = 0; k < 16; k++) {
            float a[8], b[8];
            *(float4*)&a[0] = *(const float4*)&As[cur][k][rm];
            *(float4*)&a[4] = *(const float4*)&As[cur][k][rm + 64];
            *(float4*)&b[0] = *(const float4*)&Bs[cur][k][cn];
            *(float4*)&b[4] = *(const float4*)&Bs[cur][k][cn + 64];
            #pragma unroll
            for (int i = 0; i < 8; i++)
                #pragma unroll
                for (int j = 0; j < 8; j++)
                    acc[i][j] = fmaf(a[i], b[j], acc[i][j]);
        }
        if (more) {
            const int nxt = cur ^ 1;
            As[nxt][ac+0][ar] = na0.x; As[nxt][ac+1][ar] = na0.y;
            As[nxt][ac+2][ar] = na0.z; As[nxt][ac+3][ar] = na0.w;
            As[nxt][ac+0][ar+64] = na1.x; As[nxt][ac+1][ar+64] = na1.y;
            As[nxt][ac+2][ar+64] = na1.z; As[nxt][ac+3][ar+64] = na1.w;
            *(float4*)&Bs[nxt][br][bc] = nb0;
            *(float4*)&Bs[nxt][br+8][bc] = nb1;
        }
    }

    // Epilogue
    #pragma unroll
    for (int ii = 0; ii < 8; ii++) {
        const int row = mB * 128 + rm + ((ii < 4) ? ii : 64 + (ii - 4));
        #pragma unroll
        for (int jj = 0; jj < 8; jj++) {
            const int col = nB * 128 + cn + ((jj < 4) ? jj : 64 + (jj - 4));
            float v = acc[ii][jj] + bias[col];
            if (MODE == 0) {
                const int b = row >> 11;          // /2048
                const int t = row & 2047;
                const int which = col >> 10;      // 0=q 1=k 2=v
                const int cj = col & 1023;
                const int h = cj >> 6;
                const int d = cj & 63;
                const int idx = (((b * HH + h) * TT) + t) * HD + d;
                if (which == 0)      g_q[idx] = v;
                else if (which == 1) out0[idx] = v;
                else                 out1[idx] = v;
            } else {
                out0[(size_t)row * N + col] = v;
            }
        }
    }
}

// ---------------------------------------------------------------------------
// Flash-attention v2 (causal), fp32, vectorized. One block = (b,h) x 64 q.
// 256 threads; thread (ty,tx) owns rows ty*4..+3, cols {tx+16j, j=0..3}.
// V stored transposed in smem so PV inner loop vectorizes along key dim.
// ---------------------------------------------------------------------------
#define AS 68
#define ATT_SMEM (4 * 64 * AS * (int)sizeof(float))

__global__ __launch_bounds__(256)
void attn_kernel(const float* __restrict__ Kg, const float* __restrict__ Vg)
{
    extern __shared__ float smx[];
    float* Qs = smx;                 // [64][AS] row=q, col=d
    float* Ks = Qs + 64 * AS;        // [64][AS] row=k, col=d
    float* Vt = Ks + 64 * AS;        // [64][AS] row=d, col=k (transposed)
    float* Ps = Vt + 64 * AS;        // [64][AS] row=q, col=k

    const int tid = threadIdx.x;
    const int bh = blockIdx.y;
    const int qt = gridDim.x - 1 - blockIdx.x;   // long blocks first
    const int q0 = qt * 64;

    const float* Qb = g_q + (size_t)bh * TT * HD;
    const float* Kb = Kg  + (size_t)bh * TT * HD;
    const float* Vb = Vg  + (size_t)bh * TT * HD;

    // Load Q tile [64 x 64]
    #pragma unroll
    for (int i = 0; i < 4; i++) {
        int lin = (i * 256 + tid) * 4;
        int row = lin >> 6, col = lin & 63;
        float4 v = *(const float4*)(Qb + (size_t)(q0 + row) * HD + col);
        float* d = Qs + row * AS + col;
        d[0] = v.x; d[1] = v.y; d[2] = v.z; d[3] = v.w;
    }

    const int ty = tid >> 4, tx = tid & 15;
    float m[4], l[4], o[4][4];
    #pragma unroll
    for (int i = 0; i < 4; i++) {
        m[i] = -1e30f; l[i] = 0.0f;
        #pragma unroll
        for (int j = 0; j < 4; j++) o[i][j] = 0.0f;
    }

    for (int kt = 0; kt <= qt; kt++) {
        // Load K (row-major) and V (transposed)
        #pragma unroll
        for (int i = 0; i < 4; i++) {
            int lin = (i * 256 + tid) * 4;
            int row = lin >> 6, col = lin & 63;
            float4 kv = *(const float4*)(Kb + (size_t)(kt * 64 + row) * HD + col);
            float* dk = Ks + row * AS + col;
            dk[0] = kv.x; dk[1] = kv.y; dk[2] = kv.z; dk[3] = kv.w;
            float4 vv = *(const float4*)(Vb + (size_t)(kt * 64 + row) * HD + col);
            Vt[(col + 0) * AS + row] = vv.x;
            Vt[(col + 1) * AS + row] = vv.y;
            Vt[(col + 2) * AS + row] = vv.z;
            Vt[(col + 3) * AS + row] = vv.w;
        }
        __syncthreads();

        // S = Q @ K^T, vectorized along d
        float s[4][4];
        #pragma unroll
        for (int i = 0; i < 4; i++)
            #pragma unroll
            for (int j = 0; j < 4; j++) s[i][j] = 0.0f;

        #pragma unroll
        for (int d0 = 0; d0 < 64; d0 += 4) {
            float4 q[4], kk[4];
            #pragma unroll
            for (int i = 0; i < 4; i++)
                q[i] = *(const float4*)(Qs + (ty * 4 + i) * AS + d0);
            #pragma unroll
            for (int j = 0; j < 4; j++)
                kk[j] = *(const float4*)(Ks + (tx + 16 * j) * AS + d0);
            #pragma unroll
            for (int i = 0; i < 4; i++)
                #pragma unroll
                for (int j = 0; j < 4; j++) {
                    s[i][j] = fmaf(q[i].x, kk[j].x, s[i][j]);
                    s[i][j] = fmaf(q[i].y, kk[j].y, s[i][j]);
                    s[i][j] = fmaf(q[i].z, kk[j].z, s[i][j]);
                    s[i][j] = fmaf(q[i].w, kk[j].w, s[i][j]);
                }
        }

        // scale + causal mask (only diagonal tile masks)
        #pragma unroll
        for (int i = 0; i < 4; i++)
            #pragma unroll
            for (int j = 0; j < 4; j++) {
                float sv = s[i][j] * 0.125f;       // 1/sqrt(64)
                if (kt == qt && (kt * 64 + tx + 16 * j) > (q0 + ty * 4 + i))
                    sv = -1e30f;
                s[i][j] = sv;
            }

        // Online softmax per row (16 lanes of a half-warp share a row)
        #pragma unroll
        for (int i = 0; i < 4; i++) {
            float rmax = fmaxf(fmaxf(s[i][0], s[i][1]), fmaxf(s[i][2], s[i][3]));
            #pragma unroll
            for (int off = 1; off < 16; off <<= 1)
                rmax = fmaxf(rmax, __shfl_xor_sync(0xffffffffu, rmax, off));
            const float mnew = fmaxf(m[i], rmax);
            const float corr = __expf(m[i] - mnew);
            float p[4], rsum = 0.0f;
            #pragma unroll
            for (int j = 0; j < 4; j++) { p[j] = __expf(s[i][j] - mnew); rsum += p[j]; }
            #pragma unroll
            for (int off = 1; off < 16; off <<= 1)
                rsum += __shfl_xor_sync(0xffffffffu, rsum, off);
            l[i] = l[i] * corr + rsum;
            m[i] = mnew;
            #pragma unroll
            for (int j = 0; j < 4; j++) o[i][j] *= corr;
            #pragma unroll
            for (int j = 0; j < 4; j++)
                Ps[(ty * 4 + i) * AS + tx + 16 * j] = p[j];
        }
        __syncthreads();

        // O += P @ V, vectorized along key dim (Vt rows are d-columns)
        #pragma unroll
        for (int c0 = 0; c0 < 64; c0 += 4) {
            float4 p[4], v[4];
            #pragma unroll
            for (int i = 0; i < 4; i++)
                p[i] = *(const float4*)(Ps + (ty * 4 + i) * AS + c0);
            #pragma unroll
            for (int j = 0; j < 4; j++)
                v[j] = *(const float4*)(Vt + (tx + 16 * j) * AS + c0);
            #pragma unroll
            for (int i = 0; i < 4; i++)
                #pragma unroll
                for (int j = 0; j < 4; j++) {
                    o[i][j] = fmaf(p[i].x, v[j].x, o[i][j]);
                    o[i][j] = fmaf(p[i].y, v[j].y, o[i][j]);
                    o[i][j] = fmaf(p[i].z, v[j].z, o[i][j]);
                    o[i][j] = fmaf(p[i].w, v[j].w, o[i][j]);
                }
        }
        __syncthreads();
    }

    // Write O to y scratch in [B,T,C] layout
    const int b = bh / HH, h = bh % HH;
    #pragma unroll
    for (int i = 0; i < 4; i++) {
        const float inv = 1.0f / l[i];
        const int t = q0 + ty * 4 + i;
        #pragma unroll
        for (int j = 0; j < 4; j++)
            g_y[((size_t)(b * TT + t)) * CC + h * HD + tx + 16 * j] = o[i][j] * inv;
    }
}

// ---------------------------------------------------------------------------
extern "C" void kernel_launch(void* const* d_in, const int* in_sizes, int n_in,
                              void* d_out, int out_size)
{
    const float* x      = (const float*)d_in[0];
    const float* W_attn = (const float*)d_in[1];
    const float* b_attn = (const float*)d_in[2];
    const float* W_proj = (const float*)d_in[3];
    const float* b_proj = (const float*)d_in[4];

    float* out  = (float*)d_out;               // y: [B,T,C]
    float* kout = out  + (size_t)BB * TT * CC; // k: [B,H,T,hd]
    float* vout = kout + (size_t)BB * HH * TT * HD;

    // 1) QKV GEMM + bias + split/transpose scatter
    sgemm_kernel<0><<<dim3(QKV_N / 128, BT / 128), 256>>>(
        x, W_attn, b_attn, kout, vout, QKV_N);

    // 2) causal flash attention
    cudaFuncSetAttribute(attn_kernel,
                         cudaFuncAttributeMaxDynamicSharedMemorySize, ATT_SMEM);
    attn_kernel<<<dim3(TT / 64, BB * HH), 256, ATT_SMEM>>>(kout, vout);

    // 3) output projection + bias
    sgemm_kernel<1><<<dim3(CC / 128, BT / 128), 256>>>(
        nullptr, W_proj, b_proj, out, nullptr, CC);
}